// round 7
// baseline (speedup 1.0000x reference)
#include <cuda_runtime.h>

// Problem constants
#define L_SEQ   1024
#define BATCH   8
#define DM      512
#define NH      8
#define DH      64
#define M_ROWS  (L_SEQ * BATCH)   // 8192

// Scratch (allocation-free contract): q/k/v in [b*8+h][l][d] layout
__device__ float g_q[64 * L_SEQ * DH];
__device__ float g_k[64 * L_SEQ * DH];
__device__ float g_v[64 * L_SEQ * DH];
__device__ float g_attn[M_ROWS * DM];   // [l*8+b][h*64+d]

// ---------------------------------------------------------------------------
// TF32 helpers
// ---------------------------------------------------------------------------
__device__ __forceinline__ unsigned f2tf(float x) {
    unsigned u; asm("cvt.rna.tf32.f32 %0, %1;" : "=r"(u) : "f"(x)); return u;
}
__device__ __forceinline__ float f2tf_f(float x) { return __uint_as_float(f2tf(x)); }
__device__ __forceinline__ unsigned U(float x) { return __float_as_uint(x); }

// D += A(16x8 row) * B(8x8 col), fp32 accum, tf32 inputs
__device__ __forceinline__ void mma8(float* d, const unsigned* a, const unsigned* b) {
    asm volatile("mma.sync.aligned.m16n8k8.row.col.f32.tf32.tf32.f32 "
        "{%0,%1,%2,%3}, {%4,%5,%6,%7}, {%8,%9}, {%0,%1,%2,%3};"
        : "+f"(d[0]), "+f"(d[1]), "+f"(d[2]), "+f"(d[3])
        : "r"(a[0]), "r"(a[1]), "r"(a[2]), "r"(a[3]), "r"(b[0]), "r"(b[1]));
}

// ---------------------------------------------------------------------------
// TF32 tensor-core GEMM, double-buffered: Y = X[M,512] @ W[512,512] + bias
// Block 256 thr = 8 warps (4m x 2n), BM=128, BN=64, BK=16, warptile 32x32.
// Xs pair-permuted: a-frags load as float2 (LDS.64), conflict-free.
// mode 0: Y row-major [M,512];  mode 1: scatter to [b*8+h][l][d]
// ---------------------------------------------------------------------------
#define XS_STRIDE 24    // floats per row (12 pair units)
#define WS_STRIDE 72

__global__ __launch_bounds__(256)
void gemm_tc(const float* __restrict__ X, const float* __restrict__ W,
             const float* __restrict__ bias, float* __restrict__ Y, int mode)
{
    __shared__ float Xs[2 * 128 * XS_STRIDE];
    __shared__ float Ws[2 * 16 * WS_STRIDE];

    const int tid  = threadIdx.x;
    const int lane = tid & 31;
    const int wid  = tid >> 5;
    const int wm   = wid & 3;
    const int wn   = wid >> 2;
    const int g    = lane >> 2;
    const int t4   = lane & 3;
    const int r0   = blockIdx.y * 128;
    const int n0   = blockIdx.x * 64;

    // fill-thread mapping
    const int xrow = tid >> 1;            // 0..127
    const int xkh  = (tid & 1) * 8;       // 0 or 8
    const int xpub = xkh >> 1;            // pu base: 0 or 4
    const int xrsw = 2 * ((xrow >> 2) & 1);
    const int wrow = tid >> 4;            // 0..15
    const int wc4  = (tid & 15) * 4;

    float4 xa, xb, wv;
    // prologue: load chunk 0
    xa = *(const float4*)&X[(r0 + xrow) * DM + xkh];
    xb = *(const float4*)&X[(r0 + xrow) * DM + xkh + 4];
    wv = *(const float4*)&W[wrow * DM + n0 + wc4];

    {
        float ax[4] = {xa.x, xa.y, xa.z, xa.w};
        float bx[4] = {xb.x, xb.y, xb.z, xb.w};
        float wx[4] = {wv.x, wv.y, wv.z, wv.w};
#pragma unroll
        for (int j = 0; j < 4; j++) {
            int phys = (xpub + j + xrsw) & 7;
            float2 v; v.x = f2tf_f(ax[j]); v.y = f2tf_f(bx[j]);
            *(float2*)&Xs[xrow * XS_STRIDE + 2 * phys] = v;
            Ws[wrow * WS_STRIDE + wc4 + j] = f2tf_f(wx[j]);
        }
    }
    __syncthreads();

    float acc[2][4][4];
#pragma unroll
    for (int mt = 0; mt < 2; mt++)
#pragma unroll
        for (int nt = 0; nt < 4; nt++)
#pragma unroll
            for (int i = 0; i < 4; i++) acc[mt][nt][i] = 0.f;

    const int arsw = 2 * ((g >> 2) & 1);   // (rr>>2)&1 == (g>>2)&1 here
    const int rrA  = wm * 32 + g;          // mt=0 row
    const int rrB  = wm * 32 + 16 + g;     // mt=1 row

    for (int it = 0; it < 32; it++) {
        const int buf = it & 1;
        const float* Xb = &Xs[buf * 128 * XS_STRIDE];
        const float* Wb = &Ws[buf * 16 * WS_STRIDE];

        if (it < 31) {
            int k0 = (it + 1) * 16;
            xa = *(const float4*)&X[(r0 + xrow) * DM + k0 + xkh];
            xb = *(const float4*)&X[(r0 + xrow) * DM + k0 + xkh + 4];
            wv = *(const float4*)&W[(k0 + wrow) * DM + n0 + wc4];
        }

#pragma unroll
        for (int k8 = 0; k8 < 2; k8++) {
            int phys = (4 * k8 + t4 + arsw) & 7;
            float2 a0 = *(const float2*)&Xb[rrA * XS_STRIDE + 2 * phys];
            float2 a1 = *(const float2*)&Xb[(rrA + 8) * XS_STRIDE + 2 * phys];
            float2 a2 = *(const float2*)&Xb[rrB * XS_STRIDE + 2 * phys];
            float2 a3 = *(const float2*)&Xb[(rrB + 8) * XS_STRIDE + 2 * phys];
            unsigned aA[4] = {U(a0.x), U(a1.x), U(a0.y), U(a1.y)};
            unsigned aB[4] = {U(a2.x), U(a3.x), U(a2.y), U(a3.y)};
#pragma unroll
            for (int nt = 0; nt < 4; nt++) {
                unsigned bb[2];
                bb[0] = U(Wb[(k8 * 8 + t4) * WS_STRIDE + wn * 32 + nt * 8 + g]);
                bb[1] = U(Wb[(k8 * 8 + t4 + 4) * WS_STRIDE + wn * 32 + nt * 8 + g]);
                mma8(acc[0][nt], aA, bb);
                mma8(acc[1][nt], aB, bb);
            }
        }

        if (it < 31) {
            float* Xn = &Xs[(buf ^ 1) * 128 * XS_STRIDE];
            float* Wn = &Ws[(buf ^ 1) * 16 * WS_STRIDE];
            float ax[4] = {xa.x, xa.y, xa.z, xa.w};
            float bx[4] = {xb.x, xb.y, xb.z, xb.w};
            float wx[4] = {wv.x, wv.y, wv.z, wv.w};
#pragma unroll
            for (int j = 0; j < 4; j++) {
                int phys = (xpub + j + xrsw) & 7;
                float2 v; v.x = f2tf_f(ax[j]); v.y = f2tf_f(bx[j]);
                *(float2*)&Xn[xrow * XS_STRIDE + 2 * phys] = v;
                Wn[wrow * WS_STRIDE + wc4 + j] = f2tf_f(wx[j]);
            }
        }
        __syncthreads();
    }

    // epilogue: bias + store
#pragma unroll
    for (int mt = 0; mt < 2; mt++) {
#pragma unroll
        for (int nt = 0; nt < 4; nt++) {
            int c  = n0 + wn * 32 + nt * 8 + 2 * t4;
            float b0 = bias[c], b1 = bias[c + 1];
            int rA = r0 + wm * 32 + mt * 16 + g;
            int rB = rA + 8;
            float2 vA; vA.x = acc[mt][nt][0] + b0; vA.y = acc[mt][nt][1] + b1;
            float2 vB; vB.x = acc[mt][nt][2] + b0; vB.y = acc[mt][nt][3] + b1;
            if (mode == 0) {
                *(float2*)&Y[rA * DM + c] = vA;
                *(float2*)&Y[rB * DM + c] = vB;
            } else {
                int h = c >> 6, d = c & 63;
                int lA = rA >> 3, bA = rA & 7;
                int lB = rB >> 3, bB = rB & 7;
                *(float2*)&Y[((bA * 8 + h) * L_SEQ + lA) * DH + d] = vA;
                *(float2*)&Y[((bB * 8 + h) * L_SEQ + lB) * DH + d] = vB;
            }
        }
    }
}

// ---------------------------------------------------------------------------
// Flash attention on tensor cores, pair-permuted smem, Q-frags in registers.
// Block 128 thr = 4 warps. Q-tile 64 rows, key tile 32.
// Warp w owns S/O rows 16w..16w+15. All fragment loads are LDS.64,
// conflict-free by construction (XOR swizzles verified per-buffer).
// grid: (L/64, 64 bh)
// ---------------------------------------------------------------------------
#define KS_STRIDE 72   // floats per key row (32 d-pairs + pad)
#define VS_STRIDE 40   // floats per d row  (16 key-pairs + pad)
#define PS_STRIDE 40   // floats per q row  (16 key-pairs + pad)

__global__ __launch_bounds__(128)
void attn_tc(const float* __restrict__ gq, const float* __restrict__ gk,
             const float* __restrict__ gv, float* __restrict__ out)
{
    __shared__ float Ks [32 * KS_STRIDE];   // [key][d-pairs]  (pairs along d)
    __shared__ float Vst[64 * VS_STRIDE];   // [d][key-pairs]  (pairs along key)
    __shared__ float Ps [64 * PS_STRIDE];   // [row][key-pairs]

    const int tid  = threadIdx.x;
    const int lane = tid & 31;
    const int w    = tid >> 5;
    const int g    = lane >> 2;
    const int t4   = lane & 3;
    const int bh   = blockIdx.y;
    const int b    = bh >> 3;
    const int h    = bh & 7;
    const float* qb = gq + bh * (L_SEQ * DH);
    const float* kb = gk + bh * (L_SEQ * DH);
    const float* vb = gv + bh * (L_SEQ * DH);
    const int q0 = blockIdx.x * 64;

    const int rr0 = w * 16 + g;
    const int rr1 = rr0 + 8;

    // Q fragments in registers (loop-invariant), pre-scaled by 1/sqrt(64)
    unsigned qa[8][4];
    {
        const float* q0p = qb + (q0 + rr0) * DH;
        const float* q1p = qb + (q0 + rr1) * DH;
#pragma unroll
        for (int k8 = 0; k8 < 8; k8++) {
            qa[k8][0] = f2tf(q0p[k8 * 8 + t4    ] * 0.125f);
            qa[k8][1] = f2tf(q1p[k8 * 8 + t4    ] * 0.125f);
            qa[k8][2] = f2tf(q0p[k8 * 8 + t4 + 4] * 0.125f);
            qa[k8][3] = f2tf(q1p[k8 * 8 + t4 + 4] * 0.125f);
        }
    }

    float m0 = -1e30f, m1 = -1e30f, l0 = 0.f, l1 = 0.f;
    float acco[8][4];
#pragma unroll
    for (int j = 0; j < 8; j++)
#pragma unroll
        for (int i = 0; i < 4; i++) acco[j][i] = 0.f;

    for (int kt = 0; kt < L_SEQ / 32; kt++) {
        const int k0 = kt * 32;
        __syncthreads();   // prev PV done reading Vst

        // fill K (pairs along d, self-swizzled) and V (transposed, pairs along
        // key, swizzled by d>>2). Coalesced float4 global loads.
#pragma unroll
        for (int i = 0; i < 4; i++) {
            int f4  = i * 128 + tid;
            int key = f4 >> 4;
            int c4  = (f4 & 15) * 4;
            float4 kk = *(const float4*)&kb[(k0 + key) * DH + c4];
            float4 vv = *(const float4*)&vb[(k0 + key) * DH + c4];
            float ka[4] = {kk.x, kk.y, kk.z, kk.w};
            float va[4] = {vv.x, vv.y, vv.z, vv.w};
            int vpu = 4 * (key >> 3) + (key & 3);
            int ve  = (key >> 2) & 1;
#pragma unroll
            for (int j = 0; j < 4; j++) {
                int d = c4 + j;
                int pu   = 4 * (d >> 3) + j;           // d&3 == j
                int phys = pu ^ ((pu >> 4) << 1);
                Ks[key * KS_STRIDE + 2 * phys + ((d >> 2) & 1)] = f2tf_f(ka[j]);
                int physv = vpu ^ ((d >> 2) & 15);
                Vst[d * VS_STRIDE + 2 * physv + ve] = f2tf_f(va[j]);
            }
        }
        __syncthreads();

        // ---- S = Q.K^T ----
        float accs[4][4];
#pragma unroll
        for (int j = 0; j < 4; j++)
#pragma unroll
            for (int i = 0; i < 4; i++) accs[j][i] = 0.f;

#pragma unroll
        for (int k8 = 0; k8 < 8; k8++) {
            int pu   = 4 * k8 + t4;
            int phys = pu ^ ((pu >> 4) << 1);
#pragma unroll
            for (int j = 0; j < 4; j++) {
                float2 b2 = *(const float2*)&Ks[(j * 8 + g) * KS_STRIDE + 2 * phys];
                unsigned bb[2] = {U(b2.x), U(b2.y)};
                mma8(accs[j], qa[k8], bb);
            }
        }

        // ---- online softmax ----
        float tmax0 = -1e30f, tmax1 = -1e30f;
#pragma unroll
        for (int j = 0; j < 4; j++) {
            tmax0 = fmaxf(tmax0, fmaxf(accs[j][0], accs[j][1]));
            tmax1 = fmaxf(tmax1, fmaxf(accs[j][2], accs[j][3]));
        }
        tmax0 = fmaxf(tmax0, __shfl_xor_sync(0xffffffffu, tmax0, 1));
        tmax0 = fmaxf(tmax0, __shfl_xor_sync(0xffffffffu, tmax0, 2));
        tmax1 = fmaxf(tmax1, __shfl_xor_sync(0xffffffffu, tmax1, 1));
        tmax1 = fmaxf(tmax1, __shfl_xor_sync(0xffffffffu, tmax1, 2));

        float mn0 = fmaxf(m0, tmax0);
        float mn1 = fmaxf(m1, tmax1);
        float corr0 = __expf(m0 - mn0);
        float corr1 = __expf(m1 - mn1);
        m0 = mn0; m1 = mn1;

        float p[4][4];
        float ps0 = 0.f, ps1 = 0.f;
#pragma unroll
        for (int j = 0; j < 4; j++) {
            p[j][0] = __expf(accs[j][0] - mn0);
            p[j][1] = __expf(accs[j][1] - mn0);
            p[j][2] = __expf(accs[j][2] - mn1);
            p[j][3] = __expf(accs[j][3] - mn1);
            ps0 += p[j][0] + p[j][1];
            ps1 += p[j][2] + p[j][3];
        }
        ps0 += __shfl_xor_sync(0xffffffffu, ps0, 1);
        ps0 += __shfl_xor_sync(0xffffffffu, ps0, 2);
        ps1 += __shfl_xor_sync(0xffffffffu, ps1, 1);
        ps1 += __shfl_xor_sync(0xffffffffu, ps1, 2);
        l0 = l0 * corr0 + ps0;
        l1 = l1 * corr1 + ps1;

#pragma unroll
        for (int j = 0; j < 8; j++) {
            acco[j][0] *= corr0; acco[j][1] *= corr0;
            acco[j][2] *= corr1; acco[j][3] *= corr1;
        }

        // write P into pair-permuted layout (own warp rows only)
        {
            int pub = (2 * t4) & 3;       // 0,2,0,2
            int e   = t4 >> 1;            // 0,0,1,1
#pragma unroll
            for (int j = 0; j < 4; j++) {
                int pu = 4 * j + pub;
                Ps[rr0 * PS_STRIDE + 2 * pu + e]       = f2tf_f(p[j][0]);
                Ps[rr0 * PS_STRIDE + 2 * (pu + 1) + e] = f2tf_f(p[j][1]);
                Ps[rr1 * PS_STRIDE + 2 * pu + e]       = f2tf_f(p[j][2]);
                Ps[rr1 * PS_STRIDE + 2 * (pu + 1) + e] = f2tf_f(p[j][3]);
            }
        }
        __syncwarp();

        // ---- O += P.V ----
#pragma unroll
        for (int k8 = 0; k8 < 4; k8++) {
            float2 a0 = *(const float2*)&Ps[rr0 * PS_STRIDE + 2 * (4 * k8 + t4)];
            float2 a1 = *(const float2*)&Ps[rr1 * PS_STRIDE + 2 * (4 * k8 + t4)];
            unsigned a[4] = {U(a0.x), U(a1.x), U(a0.y), U(a1.y)};
#pragma unroll
            for (int j = 0; j < 8; j++) {
                int d    = j * 8 + g;
                int phys = (4 * k8 + t4) ^ ((d >> 2) & 15);
                float2 b2 = *(const float2*)&Vst[d * VS_STRIDE + 2 * phys];
                unsigned bb[2] = {U(b2.x), U(b2.y)};
                mma8(acco[j], a, bb);
            }
        }
    }

    // epilogue: normalize, write to [l*8+b][h*64+d]
    const float inv0 = 1.f / l0;
    const float inv1 = 1.f / l1;
    const int qg0 = q0 + rr0;
    const int qg1 = q0 + rr1;
#pragma unroll
    for (int j = 0; j < 8; j++) {
        int c = j * 8 + 2 * t4;
        float2 oa; oa.x = acco[j][0] * inv0; oa.y = acco[j][1] * inv0;
        float2 ob; ob.x = acco[j][2] * inv1; ob.y = acco[j][3] * inv1;
        *(float2*)&out[(qg0 * 8 + b) * DM + h * DH + c] = oa;
        *(float2*)&out[(qg1 * 8 + b) * DM + h * DH + c] = ob;
    }
}

// ---------------------------------------------------------------------------
extern "C" void kernel_launch(void* const* d_in, const int* in_sizes, int n_in,
                              void* d_out, int out_size)
{
    const float* Q    = (const float*)d_in[0];
    const float* K    = (const float*)d_in[1];
    const float* V    = (const float*)d_in[2];
    const float* Wq   = (const float*)d_in[4];
    const float* bq   = (const float*)d_in[5];
    const float* Wk   = (const float*)d_in[6];
    const float* bk   = (const float*)d_in[7];
    const float* Wv   = (const float*)d_in[8];
    const float* bv   = (const float*)d_in[9];
    const float* Wo   = (const float*)d_in[10];
    const float* bo   = (const float*)d_in[11];
    float* out = (float*)d_out;

    float *gq, *gk, *gv, *gattn;
    cudaGetSymbolAddress((void**)&gq, g_q);
    cudaGetSymbolAddress((void**)&gk, g_k);
    cudaGetSymbolAddress((void**)&gv, g_v);
    cudaGetSymbolAddress((void**)&gattn, g_attn);

    dim3 ggrid(DM / 64, M_ROWS / 128);   // (8, 64)
    gemm_tc<<<ggrid, 256>>>(Q, Wq, bq, gq, 1);
    gemm_tc<<<ggrid, 256>>>(K, Wk, bk, gk, 1);
    gemm_tc<<<ggrid, 256>>>(V, Wv, bv, gv, 1);

    attn_tc<<<dim3(L_SEQ / 64, 64), 128>>>(gq, gk, gv, gattn);

    gemm_tc<<<ggrid, 256>>>(gattn, Wo, bo, out, 0);
}

// round 9
// speedup vs baseline: 1.2165x; 1.2165x over previous
#include <cuda_runtime.h>

// Problem constants
#define L_SEQ   1024
#define BATCH   8
#define DM      512
#define NH      8
#define DH      64
#define M_ROWS  (L_SEQ * BATCH)   // 8192

// Scratch (allocation-free contract): q/k/v in [b*8+h][l][d] layout
__device__ float g_q[64 * L_SEQ * DH];
__device__ float g_k[64 * L_SEQ * DH];
__device__ float g_v[64 * L_SEQ * DH];
__device__ float g_attn[M_ROWS * DM];   // [l*8+b][h*64+d]

// ---------------------------------------------------------------------------
// TF32 helpers
// ---------------------------------------------------------------------------
__device__ __forceinline__ unsigned f2tf(float x) {
    unsigned u; asm("cvt.rna.tf32.f32 %0, %1;" : "=r"(u) : "f"(x)); return u;
}
__device__ __forceinline__ float f2tf_f(float x) { return __uint_as_float(f2tf(x)); }
__device__ __forceinline__ unsigned U(float x) { return __float_as_uint(x); }

// D += A(16x8 row) * B(8x8 col), fp32 accum, tf32 inputs
__device__ __forceinline__ void mma8(float* d, const unsigned* a, const unsigned* b) {
    asm volatile("mma.sync.aligned.m16n8k8.row.col.f32.tf32.tf32.f32 "
        "{%0,%1,%2,%3}, {%4,%5,%6,%7}, {%8,%9}, {%0,%1,%2,%3};"
        : "+f"(d[0]), "+f"(d[1]), "+f"(d[2]), "+f"(d[3])
        : "r"(a[0]), "r"(a[1]), "r"(a[2]), "r"(a[3]), "r"(b[0]), "r"(b[1]));
}

// ---------------------------------------------------------------------------
// TF32 tensor-core GEMM (round-6 version): Y = X[M,512] @ W[512,512] + bias
// Block 256 thr = 8 warps (4 x 2), BM=128, BN=64, BK=16, warptile 32x32.
// mode 0: Y row-major [M,512];  mode 1: scatter to [b*8+h][l][d]
// ---------------------------------------------------------------------------
__global__ __launch_bounds__(256)
void gemm_tc(const float* __restrict__ X, const float* __restrict__ W,
             const float* __restrict__ bias, float* __restrict__ Y, int mode)
{
    __shared__ float Xs[128][20];   // [row][k] pad 20: A-frag banks 20g+t4 distinct
    __shared__ float Ws[16][72];    // [k][n]  pad 72: B-frag banks 8t4+g distinct

    const int tid  = threadIdx.x;
    const int lane = tid & 31;
    const int wid  = tid >> 5;
    const int wm   = wid & 3;
    const int wn   = wid >> 2;
    const int g    = lane >> 2;
    const int t4   = lane & 3;
    const int r0   = blockIdx.y * 128;
    const int n0   = blockIdx.x * 64;

    float acc[2][4][4];
#pragma unroll
    for (int mt = 0; mt < 2; mt++)
#pragma unroll
        for (int nt = 0; nt < 4; nt++)
#pragma unroll
            for (int i = 0; i < 4; i++) acc[mt][nt][i] = 0.f;

    for (int k0 = 0; k0 < DM; k0 += 16) {
        __syncthreads();
#pragma unroll
        for (int ii = 0; ii < 2; ii++) {
            int f4  = tid * 2 + ii;
            int row = f4 >> 2;
            int c4  = (f4 & 3) * 4;
            float4 t = *(const float4*)&X[(r0 + row) * DM + k0 + c4];
            Xs[row][c4 + 0] = f2tf_f(t.x);
            Xs[row][c4 + 1] = f2tf_f(t.y);
            Xs[row][c4 + 2] = f2tf_f(t.z);
            Xs[row][c4 + 3] = f2tf_f(t.w);
        }
        {
            int row = tid >> 4;
            int c4  = (tid & 15) * 4;
            float4 t = *(const float4*)&W[(k0 + row) * DM + n0 + c4];
            Ws[row][c4 + 0] = f2tf_f(t.x);
            Ws[row][c4 + 1] = f2tf_f(t.y);
            Ws[row][c4 + 2] = f2tf_f(t.z);
            Ws[row][c4 + 3] = f2tf_f(t.w);
        }
        __syncthreads();

#pragma unroll
        for (int k8 = 0; k8 < 2; k8++) {
            unsigned a[2][4];
#pragma unroll
            for (int mt = 0; mt < 2; mt++) {
                int rr = wm * 32 + mt * 16 + g;
                a[mt][0] = U(Xs[rr    ][k8 * 8 + t4    ]);
                a[mt][1] = U(Xs[rr + 8][k8 * 8 + t4    ]);
                a[mt][2] = U(Xs[rr    ][k8 * 8 + t4 + 4]);
                a[mt][3] = U(Xs[rr + 8][k8 * 8 + t4 + 4]);
            }
#pragma unroll
            for (int nt = 0; nt < 4; nt++) {
                unsigned bb[2];
                bb[0] = U(Ws[k8 * 8 + t4    ][wn * 32 + nt * 8 + g]);
                bb[1] = U(Ws[k8 * 8 + t4 + 4][wn * 32 + nt * 8 + g]);
                mma8(acc[0][nt], a[0], bb);
                mma8(acc[1][nt], a[1], bb);
            }
        }
    }

    // epilogue: bias + store
#pragma unroll
    for (int mt = 0; mt < 2; mt++) {
#pragma unroll
        for (int nt = 0; nt < 4; nt++) {
            int c  = n0 + wn * 32 + nt * 8 + 2 * t4;
            float b0 = bias[c], b1 = bias[c + 1];
            int rA = r0 + wm * 32 + mt * 16 + g;
            int rB = rA + 8;
            float2 vA; vA.x = acc[mt][nt][0] + b0; vA.y = acc[mt][nt][1] + b1;
            float2 vB; vB.x = acc[mt][nt][2] + b0; vB.y = acc[mt][nt][3] + b1;
            if (mode == 0) {
                *(float2*)&Y[rA * DM + c] = vA;
                *(float2*)&Y[rB * DM + c] = vB;
            } else {
                int h = c >> 6, d = c & 63;
                int lA = rA >> 3, bA = rA & 7;
                int lB = rB >> 3, bB = rB & 7;
                *(float2*)&Y[((bA * 8 + h) * L_SEQ + lA) * DH + d] = vA;
                *(float2*)&Y[((bB * 8 + h) * L_SEQ + lB) * DH + d] = vB;
            }
        }
    }
}

// ---------------------------------------------------------------------------
// Flash attention on tensor cores. All operands in pair-permuted smem so every
// fragment load is one LDS.64.
// Q/K: pairs along d -> 32 pairs = 64 floats/row, stride 72 (36 float2 units,
//      36 mod 32 = 4 -> fragment banks (4*row + pu) mod 32 all distinct).
// V:   transposed, pairs along key (16 pairs), XOR swizzle by d>>2, stride 40.
// P:   pairs along key, stride 40.
// Block 128 thr = 4 warps; Q-tile 64 rows, key tile 32; warp w owns rows
// 16w..16w+15. grid: (L/64, 64 bh)
// ---------------------------------------------------------------------------
#define QS_STRIDE 72   // floats per q row   (64 d-floats as 32 pairs + pad)
#define KS_STRIDE 72   // floats per key row (64 d-floats as 32 pairs + pad)
#define VS_STRIDE 40   // floats per d row   (32 key-floats as 16 pairs + pad)
#define PS_STRIDE 40   // floats per q row   (32 key-floats as 16 pairs + pad)

__global__ __launch_bounds__(128, 4)
void attn_tc(const float* __restrict__ gq, const float* __restrict__ gk,
             const float* __restrict__ gv, float* __restrict__ out)
{
    __shared__ float Qs [64 * QS_STRIDE];   // 18.0 KB
    __shared__ float Ks [32 * KS_STRIDE];   //  9.0 KB
    __shared__ float Vst[64 * VS_STRIDE];   // 10.0 KB
    __shared__ float Ps [64 * PS_STRIDE];   // 10.0 KB  -> 47 KB total

    const int tid  = threadIdx.x;
    const int lane = tid & 31;
    const int w    = tid >> 5;
    const int g    = lane >> 2;
    const int t4   = lane & 3;
    const int bh   = blockIdx.y;
    const int b    = bh >> 3;
    const int h    = bh & 7;
    const float* qb = gq + bh * (L_SEQ * DH);
    const float* kb = gk + bh * (L_SEQ * DH);
    const float* vb = gv + bh * (L_SEQ * DH);
    const int q0 = blockIdx.x * 64;

    const int rr0 = w * 16 + g;
    const int rr1 = rr0 + 8;

    // fill Q tile: pair unit pu = 4*(d>>3) + (d&3), elem e = (d>>2)&1.
    // pre-scaled by 1/sqrt(64), tf32-rounded.
#pragma unroll
    for (int i = 0; i < 8; i++) {
        int f4  = i * 128 + tid;
        int row = f4 >> 4;
        int c4  = (f4 & 15) * 4;
        float4 t = *(const float4*)&qb[(q0 + row) * DH + c4];
        float qa4[4] = {t.x, t.y, t.z, t.w};
#pragma unroll
        for (int j = 0; j < 4; j++) {
            int d  = c4 + j;
            int pu = 4 * (d >> 3) + j;
            Qs[row * QS_STRIDE + 2 * pu + ((d >> 2) & 1)] = f2tf_f(qa4[j] * 0.125f);
        }
    }

    float m0 = -1e30f, m1 = -1e30f, l0 = 0.f, l1 = 0.f;
    float acco[8][4];
#pragma unroll
    for (int j = 0; j < 8; j++)
#pragma unroll
        for (int i = 0; i < 4; i++) acco[j][i] = 0.f;

    for (int kt = 0; kt < L_SEQ / 32; kt++) {
        const int k0 = kt * 32;
        __syncthreads();   // prev PV done reading Vst; Qs visible (kt=0)

        // fill K (pairs along d) and V (transposed, pairs along key, XOR-swizzled)
#pragma unroll
        for (int i = 0; i < 4; i++) {
            int f4  = i * 128 + tid;
            int key = f4 >> 4;
            int c4  = (f4 & 15) * 4;
            float4 kk = *(const float4*)&kb[(k0 + key) * DH + c4];
            float4 vv = *(const float4*)&vb[(k0 + key) * DH + c4];
            float ka[4] = {kk.x, kk.y, kk.z, kk.w};
            float va[4] = {vv.x, vv.y, vv.z, vv.w};
            int vpu = 4 * (key >> 3) + (key & 3);
            int ve  = (key >> 2) & 1;
#pragma unroll
            for (int j = 0; j < 4; j++) {
                int d  = c4 + j;
                int pu = 4 * (d >> 3) + j;
                Ks[key * KS_STRIDE + 2 * pu + ((d >> 2) & 1)] = f2tf_f(ka[j]);
                int physv = vpu ^ ((d >> 2) & 15);
                Vst[d * VS_STRIDE + 2 * physv + ve] = f2tf_f(va[j]);
            }
        }
        __syncthreads();

        // ---- S = Q.K^T : one LDS.64 per fragment pair ----
        float accs[4][4];
#pragma unroll
        for (int j = 0; j < 4; j++)
#pragma unroll
            for (int i = 0; i < 4; i++) accs[j][i] = 0.f;

#pragma unroll
        for (int k8 = 0; k8 < 8; k8++) {
            int pu = 4 * k8 + t4;
            float2 q0p = *(const float2*)&Qs[rr0 * QS_STRIDE + 2 * pu];
            float2 q1p = *(const float2*)&Qs[rr1 * QS_STRIDE + 2 * pu];
            unsigned a[4] = {U(q0p.x), U(q1p.x), U(q0p.y), U(q1p.y)};
#pragma unroll
            for (int j = 0; j < 4; j++) {
                float2 b2 = *(const float2*)&Ks[(j * 8 + g) * KS_STRIDE + 2 * pu];
                unsigned bb[2] = {U(b2.x), U(b2.y)};
                mma8(accs[j], a, bb);
            }
        }

        // ---- online softmax ----
        float tmax0 = -1e30f, tmax1 = -1e30f;
#pragma unroll
        for (int j = 0; j < 4; j++) {
            tmax0 = fmaxf(tmax0, fmaxf(accs[j][0], accs[j][1]));
            tmax1 = fmaxf(tmax1, fmaxf(accs[j][2], accs[j][3]));
        }
        tmax0 = fmaxf(tmax0, __shfl_xor_sync(0xffffffffu, tmax0, 1));
        tmax0 = fmaxf(tmax0, __shfl_xor_sync(0xffffffffu, tmax0, 2));
        tmax1 = fmaxf(tmax1, __shfl_xor_sync(0xffffffffu, tmax1, 1));
        tmax1 = fmaxf(tmax1, __shfl_xor_sync(0xffffffffu, tmax1, 2));

        float mn0 = fmaxf(m0, tmax0);
        float mn1 = fmaxf(m1, tmax1);
        float corr0 = __expf(m0 - mn0);
        float corr1 = __expf(m1 - mn1);
        m0 = mn0; m1 = mn1;

        float p[4][4];
        float ps0 = 0.f, ps1 = 0.f;
#pragma unroll
        for (int j = 0; j < 4; j++) {
            p[j][0] = __expf(accs[j][0] - mn0);
            p[j][1] = __expf(accs[j][1] - mn0);
            p[j][2] = __expf(accs[j][2] - mn1);
            p[j][3] = __expf(accs[j][3] - mn1);
            ps0 += p[j][0] + p[j][1];
            ps1 += p[j][2] + p[j][3];
        }
        ps0 += __shfl_xor_sync(0xffffffffu, ps0, 1);
        ps0 += __shfl_xor_sync(0xffffffffu, ps0, 2);
        ps1 += __shfl_xor_sync(0xffffffffu, ps1, 1);
        ps1 += __shfl_xor_sync(0xffffffffu, ps1, 2);
        l0 = l0 * corr0 + ps0;
        l1 = l1 * corr1 + ps1;

#pragma unroll
        for (int j = 0; j < 8; j++) {
            acco[j][0] *= corr0; acco[j][1] *= corr0;
            acco[j][2] *= corr1; acco[j][3] *= corr1;
        }

        // write P into pair layout (own warp rows only):
        // key = j*8 + 2*t4 (+1) -> pu = 4j + ((2t4)&3) (+1), e = t4>>1
        {
            int pub = (2 * t4) & 3;
            int e   = t4 >> 1;
#pragma unroll
            for (int j = 0; j < 4; j++) {
                int pu = 4 * j + pub;
                Ps[rr0 * PS_STRIDE + 2 * pu + e]       = f2tf_f(p[j][0]);
                Ps[rr0 * PS_STRIDE + 2 * (pu + 1) + e] = f2tf_f(p[j][1]);
                Ps[rr1 * PS_STRIDE + 2 * pu + e]       = f2tf_f(p[j][2]);
                Ps[rr1 * PS_STRIDE + 2 * (pu + 1) + e] = f2tf_f(p[j][3]);
            }
        }
        __syncwarp();

        // ---- O += P.V ----
#pragma unroll
        for (int k8 = 0; k8 < 4; k8++) {
            float2 a0 = *(const float2*)&Ps[rr0 * PS_STRIDE + 2 * (4 * k8 + t4)];
            float2 a1 = *(const float2*)&Ps[rr1 * PS_STRIDE + 2 * (4 * k8 + t4)];
            unsigned a[4] = {U(a0.x), U(a1.x), U(a0.y), U(a1.y)};
#pragma unroll
            for (int j = 0; j < 8; j++) {
                int d    = j * 8 + g;
                int phys = (4 * k8 + t4) ^ ((d >> 2) & 15);
                float2 b2 = *(const float2*)&Vst[d * VS_STRIDE + 2 * phys];
                unsigned bb[2] = {U(b2.x), U(b2.y)};
                mma8(acco[j], a, bb);
            }
        }
    }

    // epilogue: normalize, write to [l*8+b][h*64+d]
    const float inv0 = 1.f / l0;
    const float inv1 = 1.f / l1;
    const int qg0 = q0 + rr0;
    const int qg1 = q0 + rr1;
#pragma unroll
    for (int j = 0; j < 8; j++) {
        int c = j * 8 + 2 * t4;
        float2 oa; oa.x = acco[j][0] * inv0; oa.y = acco[j][1] * inv0;
        float2 ob; ob.x = acco[j][2] * inv1; ob.y = acco[j][3] * inv1;
        *(float2*)&out[(qg0 * 8 + b) * DM + h * DH + c] = oa;
        *(float2*)&out[(qg1 * 8 + b) * DM + h * DH + c] = ob;
    }
}

// ---------------------------------------------------------------------------
extern "C" void kernel_launch(void* const* d_in, const int* in_sizes, int n_in,
                              void* d_out, int out_size)
{
    const float* Q    = (const float*)d_in[0];
    const float* K    = (const float*)d_in[1];
    const float* V    = (const float*)d_in[2];
    const float* Wq   = (const float*)d_in[4];
    const float* bq   = (const float*)d_in[5];
    const float* Wk   = (const float*)d_in[6];
    const float* bk   = (const float*)d_in[7];
    const float* Wv   = (const float*)d_in[8];
    const float* bv   = (const float*)d_in[9];
    const float* Wo   = (const float*)d_in[10];
    const float* bo   = (const float*)d_in[11];
    float* out = (float*)d_out;

    float *gq, *gk, *gv, *gattn;
    cudaGetSymbolAddress((void**)&gq, g_q);
    cudaGetSymbolAddress((void**)&gk, g_k);
    cudaGetSymbolAddress((void**)&gv, g_v);
    cudaGetSymbolAddress((void**)&gattn, g_attn);

    dim3 ggrid(DM / 64, M_ROWS / 128);   // (8, 64)
    gemm_tc<<<ggrid, 256>>>(Q, Wq, bq, gq, 1);
    gemm_tc<<<ggrid, 256>>>(K, Wk, bk, gk, 1);
    gemm_tc<<<ggrid, 256>>>(V, Wv, bv, gv, 1);

    attn_tc<<<dim3(L_SEQ / 64, 64), 128>>>(gq, gk, gv, gattn);

    gemm_tc<<<ggrid, 256>>>(gattn, Wo, bo, out, 0);
}